// round 2
// baseline (speedup 1.0000x reference)
#include <cuda_runtime.h>
#include <cstdint>

#define HW 16384
#define NB 2

// ---------------- scratch (device globals; no allocations allowed) ----------
__device__ __align__(16) float g_xd  [NB*64*HW];   // upsample-conv-pad result
__device__ __align__(16) float g_off [NB*27*HW];   // raw offset-conv output (reused L/R)
__device__ __align__(16) float g_xl2 [NB*64*HW];   // deform-conv left out
__device__ __align__(16) float g_xr2 [NB*64*HW];   // deform-conv right out
__device__ __align__(16) float g_x0  [NB*64*HW];
__device__ __align__(16) float g_tmp [NB*64*HW];
__device__ __align__(16) float g_x1  [NB*64*HW];
__device__ __align__(16) float g_xlt [NB*HW*64];   // xl in NHWC for gathers
__device__ __align__(16) float g_xrt [NB*HW*64];   // xr in NHWC
__device__ __align__(16) float g_dlT [576*64];     // deform weights [k*64+c][o]
__device__ __align__(16) float g_drT [576*64];

// ---------------- NCHW -> NHWC transpose (per n: 64 x 16384 -> 16384 x 64) --
__global__ void k_transpose(const float* __restrict__ in, float* __restrict__ out)
{
    __shared__ float tile[32][33];
    int n  = blockIdx.z;
    int c0 = blockIdx.y * 32;
    int p0 = blockIdx.x * 32;
    int tx = threadIdx.x, ty = threadIdx.y;
    const float* src = in  + n*64*HW;
    float*       dst = out + n*HW*64;
    #pragma unroll
    for (int i = 0; i < 32; i += 8)
        tile[ty+i][tx] = src[(c0+ty+i)*HW + p0 + tx];
    __syncthreads();
    #pragma unroll
    for (int i = 0; i < 32; i += 8)
        dst[(p0+ty+i)*64 + c0 + tx] = tile[tx][ty+i];
}

// ---------------- deform weight transpose: w[o][c][k] -> wT[(k*64+c)*64+o] --
__global__ void k_prep_wT(const float* __restrict__ w, float* __restrict__ wT)
{
    int i = blockIdx.x*256 + threadIdx.x;
    if (i < 576*64){
        int o  = i & 63;
        int kc = i >> 6;
        int c  = kc & 63;
        int k  = kc >> 6;
        wT[i] = w[(o*64 + c)*9 + k];
    }
}

// ---------------- upsample(2x nearest) + 2x2 conv + pad(bottom/right) ------
// out[n][o][Y][X] for Y,X<127: sum_i sum_{dy,dx} w[o][i][dy][dx]*xd[n][i][(Y+dy)>>1][(X+dx)>>1]
// row/col 127 are zero padding (padding applied after conv+bias in reference).
__global__ void k_upconv(const float* __restrict__ xd, const float* __restrict__ w,
                         const float* __restrict__ bias, float* __restrict__ out)
{
    __shared__ float4 s_w4[2048];        // 16 oc x 128 ic x 4 taps
    __shared__ float  s_in[9*18];
    int n      = blockIdx.z;
    int ocBase = blockIdx.y * 16;
    int tx0 = (blockIdx.x & 3) * 32;
    int ty0 = (blockIdx.x >> 2) * 16;
    int t  = threadIdx.x;
    int lx = t & 31, ly = t >> 5;

    float* s_w = (float*)s_w4;
    for (int i = t; i < 8192; i += 256) s_w[i] = w[ocBase*512 + i];
    __syncthreads();

    const float* src = xd + n*128*4096;
    float accA[16], accB[16];
    #pragma unroll
    for (int oc = 0; oc < 16; oc++){ accA[oc] = 0.f; accB[oc] = 0.f; }

    int X  = tx0 + lx;
    int YA = ty0 + ly, YB = ty0 + ly + 8;
    bool doA = (YA < 127) && (X < 127);
    bool doB = (YB < 127) && (X < 127);
    int x0r = lx >> 1,      x1r = (lx+1) >> 1;
    int yA0 = ly >> 1,      yA1 = (ly+1) >> 1;
    int yB0 = (ly+8) >> 1,  yB1 = (ly+9) >> 1;

    for (int ic = 0; ic < 128; ic++){
        const float* p = src + ic*4096;
        if (t < 162){
            int r = t/18, c = t - r*18;
            int gy = (ty0>>1) + r, gx = (tx0>>1) + c;
            s_in[t] = (gy < 64 && gx < 64) ? p[gy*64 + gx] : 0.f;
        }
        __syncthreads();
        if (doA){
            float v00 = s_in[yA0*18+x0r], v01 = s_in[yA0*18+x1r];
            float v10 = s_in[yA1*18+x0r], v11 = s_in[yA1*18+x1r];
            #pragma unroll
            for (int oc = 0; oc < 16; oc++){
                float4 wv = s_w4[oc*128 + ic];
                accA[oc] += wv.x*v00 + wv.y*v01 + wv.z*v10 + wv.w*v11;
            }
        }
        if (doB){
            float v00 = s_in[yB0*18+x0r], v01 = s_in[yB0*18+x1r];
            float v10 = s_in[yB1*18+x0r], v11 = s_in[yB1*18+x1r];
            #pragma unroll
            for (int oc = 0; oc < 16; oc++){
                float4 wv = s_w4[oc*128 + ic];
                accB[oc] += wv.x*v00 + wv.y*v01 + wv.z*v10 + wv.w*v11;
            }
        }
        __syncthreads();
    }
    #pragma unroll
    for (int oc = 0; oc < 16; oc++){
        int o = ocBase + oc;
        float bv = bias[o];
        out[(n*64+o)*HW + YA*128 + X] = doA ? (accA[oc] + bv) : 0.f;
        out[(n*64+o)*HW + YB*128 + X] = doB ? (accB[oc] + bv) : 0.f;
    }
}

// ---------------- generic 3x3 conv, pad 1, virtual concat of up to 3 inputs -
// tile 32x16 px, 16 oc / block, 256 threads, 2 px x 16 oc per thread.
__global__ void k_conv3x3(const float* __restrict__ in0, const float* __restrict__ in1,
                          const float* __restrict__ in2, int nin,
                          const float* __restrict__ w, const float* __restrict__ bias,
                          float* __restrict__ out, int Cout,
                          const float* __restrict__ res, int relu)
{
    __shared__ float s_in[18*34];
    __shared__ float s_w[144];
    int n      = blockIdx.z;
    int ocBase = blockIdx.y * 16;
    int tx0 = (blockIdx.x & 3) * 32;
    int ty0 = (blockIdx.x >> 2) * 16;
    int t  = threadIdx.x;
    int lx = t & 31, ly = t >> 5;
    int Cin = nin * 64;

    float accA[16], accB[16];
    #pragma unroll
    for (int oc = 0; oc < 16; oc++){ accA[oc] = 0.f; accB[oc] = 0.f; }

    for (int ic = 0; ic < Cin; ic++){
        const float* src = (ic < 64) ? in0 : ((ic < 128) ? in1 : in2);
        src += (n*64 + (ic & 63)) * HW;
        for (int i = t; i < 612; i += 256){
            int r = i/34, c = i - r*34;
            int gy = ty0 + r - 1, gx = tx0 + c - 1;
            float v = 0.f;
            if (gy >= 0 && gy < 128 && gx >= 0 && gx < 128) v = src[gy*128 + gx];
            s_in[i] = v;
        }
        if (t < 144){
            int oc = t/9, j = t - oc*9;
            float wv = 0.f;
            if (ocBase + oc < Cout) wv = w[((ocBase+oc)*Cin + ic)*9 + j];
            s_w[t] = wv;
        }
        __syncthreads();
        float rA[9], rB[9];
        #pragma unroll
        for (int j = 0; j < 9; j++){
            int rr = j/3, cc = j - rr*3;
            rA[j] = s_in[(ly+rr)*34   + lx + cc];
            rB[j] = s_in[(ly+8+rr)*34 + lx + cc];
        }
        #pragma unroll
        for (int oc = 0; oc < 16; oc++){
            #pragma unroll
            for (int j = 0; j < 9; j++){
                float wv = s_w[oc*9 + j];
                accA[oc] = fmaf(rA[j], wv, accA[oc]);
                accB[oc] = fmaf(rB[j], wv, accB[oc]);
            }
        }
        __syncthreads();
    }
    int X = tx0 + lx;
    #pragma unroll
    for (int oc = 0; oc < 16; oc++){
        int o = ocBase + oc;
        if (o < Cout){
            float bv = bias[o];
            int idxA = (n*Cout + o)*HW + (ty0+ly)*128 + X;
            int idxB = idxA + 8*128;
            float vA = accA[oc] + bv, vB = accB[oc] + bv;
            if (res){ vA += res[idxA]; vB += res[idxB]; }
            if (relu){ vA = fmaxf(vA, 0.f); vB = fmaxf(vB, 0.f); }
            out[idxA] = vA; out[idxB] = vB;
        }
    }
}

// ---------------- modulated deformable 3x3 conv ------------------------------
// Block handles 16 pixels (2 rows x 8 cols), 256 threads.
// Phase A: per (px,k) offset/mask params. Phase B: coalesced NHWC bilinear
// gather into SMEM im2col tile. Phase C: SMEM-staged GEMM vs wT[(k*64+c)][o].
__global__ void k_deform(const float* __restrict__ xt, const float* __restrict__ off,
                         const float* __restrict__ wT, const float* __restrict__ bias,
                         float* __restrict__ out)
{
    extern __shared__ float smem[];
    float* s_samp = smem;                 // 16*576 = 9216 floats
    float* s_w    = smem + 9216;          // 144*64 = 9216 floats (kc chunk)
    float* s_wy   = smem + 18432;
    float* s_wx   = s_wy + 144;
    float* s_m    = s_wx + 144;
    int*   s_iy   = (int*)(s_m + 144);
    int*   s_ix   = s_iy + 144;

    int n  = blockIdx.z;
    int y0 = blockIdx.y * 2;
    int x0 = blockIdx.x * 8;
    int t  = threadIdx.x;

    if (t < 144){
        int p = t / 9, k = t - p*9;
        int yy = y0 + (p >> 3), xx = x0 + (p & 7);
        const float* ob = off + n*27*HW + yy*128 + xx;
        float dyv = ob[(2*k)*HW];
        float dxv = ob[(2*k+1)*HW];
        float mv  = 1.f / (1.f + __expf(-ob[(18+k)*HW]));
        float py = dyv + (float)(k/3) - 1.f + (float)yy;
        float px = dxv + (float)(k%3) - 1.f + (float)xx;
        float fy = floorf(py), fx = floorf(px);
        s_iy[t] = (int)fy;  s_ix[t] = (int)fx;
        s_wy[t] = py - fy;  s_wx[t] = px - fx;
        s_m[t]  = mv;
    }
    __syncthreads();

    int lane = t & 31, wrp = t >> 5;
    const float2* xb = (const float2*)(xt + n*HW*64);   // [(iy*128+ix)*32 + lane]
    float2* s_samp2 = (float2*)s_samp;
    for (int pp = wrp; pp < 16; pp += 8){
        #pragma unroll
        for (int k = 0; k < 9; k++){
            int pk = pp*9 + k;
            int iy0 = s_iy[pk], ix0 = s_ix[pk];
            float wy = s_wy[pk], wx = s_wx[pk], m = s_m[pk];
            float w00 = (1.f-wy)*(1.f-wx);
            float w01 = (1.f-wy)*wx;
            float w10 = wy*(1.f-wx);
            float w11 = wy*wx;
            float ax = 0.f, ay = 0.f;
            int iy1 = iy0 + 1, ix1 = ix0 + 1;
            bool y0v = (unsigned)iy0 < 128u, y1v = (unsigned)iy1 < 128u;
            bool x0v = (unsigned)ix0 < 128u, x1v = (unsigned)ix1 < 128u;
            if (y0v && x0v){ float2 v = xb[(iy0*128+ix0)*32 + lane]; ax += w00*v.x; ay += w00*v.y; }
            if (y0v && x1v){ float2 v = xb[(iy0*128+ix1)*32 + lane]; ax += w01*v.x; ay += w01*v.y; }
            if (y1v && x0v){ float2 v = xb[(iy1*128+ix0)*32 + lane]; ax += w10*v.x; ay += w10*v.y; }
            if (y1v && x1v){ float2 v = xb[(iy1*128+ix1)*32 + lane]; ax += w11*v.x; ay += w11*v.y; }
            s_samp2[pp*288 + k*32 + lane] = make_float2(m*ax, m*ay);
        }
    }
    __syncthreads();

    float2 a0 = make_float2(0.f, 0.f), a1 = make_float2(0.f, 0.f);
    int pA = wrp, pB = wrp + 8;
    for (int ch = 0; ch < 4; ch++){
        const float4* wsrc = (const float4*)(wT + ch*144*64);
        float4* wdst = (float4*)s_w;
        for (int i = t; i < 2304; i += 256) wdst[i] = wsrc[i];
        __syncthreads();
        const float2* w2 = (const float2*)s_w;
        const float* sA = s_samp + pA*576 + ch*144;
        const float* sB = s_samp + pB*576 + ch*144;
        #pragma unroll 8
        for (int kc = 0; kc < 144; kc++){
            float v0 = sA[kc];
            float v1 = sB[kc];
            float2 wv = w2[kc*32 + lane];
            a0.x = fmaf(wv.x, v0, a0.x);
            a0.y = fmaf(wv.y, v0, a0.y);
            a1.x = fmaf(wv.x, v1, a1.x);
            a1.y = fmaf(wv.y, v1, a1.y);
        }
        __syncthreads();
    }
    int o0 = 2*lane;
    float b0 = bias[o0], b1 = bias[o0+1];
    {
        int yy = y0 + (pA >> 3), xx = x0 + (pA & 7);
        int base = n*64*HW + yy*128 + xx;
        out[base + o0*HW]     = a0.x + b0;
        out[base + (o0+1)*HW] = a0.y + b1;
    }
    {
        int yy = y0 + (pB >> 3), xx = x0 + (pB & 7);
        int base = n*64*HW + yy*128 + xx;
        out[base + o0*HW]     = a1.x + b0;
        out[base + (o0+1)*HW] = a1.y + b1;
    }
}

// ---------------------------------------------------------------------------
extern "C" void kernel_launch(void* const* d_in, const int* in_sizes, int n_in,
                              void* d_out, int out_size)
{
    const float* xd     = (const float*)d_in[0];
    const float* xl     = (const float*)d_in[1];
    const float* xr     = (const float*)d_in[2];
    const float* up_w   = (const float*)d_in[3];
    const float* up_b   = (const float*)d_in[4];
    const float* offl_w = (const float*)d_in[5];
    const float* offl_b = (const float*)d_in[6];
    const float* dl_w   = (const float*)d_in[7];
    const float* dl_b   = (const float*)d_in[8];
    const float* offr_w = (const float*)d_in[9];
    const float* offr_b = (const float*)d_in[10];
    const float* dr_w   = (const float*)d_in[11];
    const float* dr_b   = (const float*)d_in[12];
    const float* cv_w   = (const float*)d_in[13];
    const float* cv_b   = (const float*)d_in[14];

    // Residual-block params. setup_inputs() inserts weights FIRST
    // (rb1_w1, rb1_w2, rb2_w1, rb2_w2) then biases (rb1_b1, rb1_b2, rb2_b1,
    // rb2_b2). Detect layout defensively via element counts: weights are
    // 64*64*9=36864 elems, biases 64.
    const float *rb1_w1, *rb1_b1, *rb1_w2, *rb1_b2;
    const float *rb2_w1, *rb2_b1, *rb2_w2, *rb2_b2;
    if (in_sizes[16] == 64){
        // interleaved: w1,b1,w2,b2, w1,b1,w2,b2
        rb1_w1 = (const float*)d_in[15]; rb1_b1 = (const float*)d_in[16];
        rb1_w2 = (const float*)d_in[17]; rb1_b2 = (const float*)d_in[18];
        rb2_w1 = (const float*)d_in[19]; rb2_b1 = (const float*)d_in[20];
        rb2_w2 = (const float*)d_in[21]; rb2_b2 = (const float*)d_in[22];
    } else {
        // grouped: rb1_w1, rb1_w2, rb2_w1, rb2_w2, rb1_b1, rb1_b2, rb2_b1, rb2_b2
        rb1_w1 = (const float*)d_in[15]; rb1_w2 = (const float*)d_in[16];
        rb2_w1 = (const float*)d_in[17]; rb2_w2 = (const float*)d_in[18];
        rb1_b1 = (const float*)d_in[19]; rb1_b2 = (const float*)d_in[20];
        rb2_b1 = (const float*)d_in[21]; rb2_b2 = (const float*)d_in[22];
    }

    float *p_xd, *p_off, *p_xl2, *p_xr2, *p_x0, *p_tmp, *p_x1, *p_xlt, *p_xrt, *p_dlT, *p_drT;
    cudaGetSymbolAddress((void**)&p_xd,  g_xd);
    cudaGetSymbolAddress((void**)&p_off, g_off);
    cudaGetSymbolAddress((void**)&p_xl2, g_xl2);
    cudaGetSymbolAddress((void**)&p_xr2, g_xr2);
    cudaGetSymbolAddress((void**)&p_x0,  g_x0);
    cudaGetSymbolAddress((void**)&p_tmp, g_tmp);
    cudaGetSymbolAddress((void**)&p_x1,  g_x1);
    cudaGetSymbolAddress((void**)&p_xlt, g_xlt);
    cudaGetSymbolAddress((void**)&p_xrt, g_xrt);
    cudaGetSymbolAddress((void**)&p_dlT, g_dlT);
    cudaGetSymbolAddress((void**)&p_drT, g_drT);

    cudaFuncSetAttribute(k_deform, cudaFuncAttributeMaxDynamicSharedMemorySize, 76608);

    dim3 tb(32, 8);
    // Prep: NHWC transposes + deform weight transposes + upsample-conv
    k_transpose<<<dim3(512, 2, 2), tb>>>(xl, p_xlt);
    k_transpose<<<dim3(512, 2, 2), tb>>>(xr, p_xrt);
    k_prep_wT<<<144, 256>>>(dl_w, p_dlT);
    k_prep_wT<<<144, 256>>>(dr_w, p_drT);
    k_upconv<<<dim3(32, 4, 2), 256>>>(xd, up_w, up_b, p_xd);

    // Left branch: offset conv (192->27) then deformable conv on original xl
    k_conv3x3<<<dim3(32, 2, 2), 256>>>(xl, xr, p_xd, 3, offl_w, offl_b, p_off, 27, nullptr, 0);
    k_deform<<<dim3(16, 64, 2), 256, 76608>>>(p_xlt, p_off, p_dlT, dl_b, p_xl2);

    // Right branch: offset conv uses updated xl
    k_conv3x3<<<dim3(32, 2, 2), 256>>>(p_xl2, xr, p_xd, 3, offr_w, offr_b, p_off, 27, nullptr, 0);
    k_deform<<<dim3(16, 64, 2), 256, 76608>>>(p_xrt, p_off, p_drT, dr_b, p_xr2);

    // Fuse conv (192->64) + ReLU
    k_conv3x3<<<dim3(32, 4, 2), 256>>>(p_xl2, p_xr2, p_xd, 3, cv_w, cv_b, p_x0, 64, nullptr, 1);

    // Residual block 1
    k_conv3x3<<<dim3(32, 4, 2), 256>>>(p_x0,  nullptr, nullptr, 1, rb1_w1, rb1_b1, p_tmp, 64, nullptr, 1);
    k_conv3x3<<<dim3(32, 4, 2), 256>>>(p_tmp, nullptr, nullptr, 1, rb1_w2, rb1_b2, p_x1,  64, p_x0,   0);

    // Residual block 2 (final conv writes straight to d_out)
    k_conv3x3<<<dim3(32, 4, 2), 256>>>(p_x1,  nullptr, nullptr, 1, rb2_w1, rb2_b1, p_tmp, 64, nullptr, 1);
    k_conv3x3<<<dim3(32, 4, 2), 256>>>(p_tmp, nullptr, nullptr, 1, rb2_w2, rb2_b2, (float*)d_out, 64, p_x1, 0);
}

// round 3
// speedup vs baseline: 1.4316x; 1.4316x over previous
#include <cuda_runtime.h>
#include <cstdint>

#define HW 16384
#define NB 2

// ---------------- scratch (device globals; no allocations allowed) ----------
__device__ __align__(16) float g_xd  [NB*64*HW];   // upsample-conv-pad result
__device__ __align__(16) float g_off [NB*27*HW];   // raw offset-conv output (reused L/R)
__device__ __align__(16) float g_xl2 [NB*64*HW];   // deform-conv left out
__device__ __align__(16) float g_xr2 [NB*64*HW];   // deform-conv right out
__device__ __align__(16) float g_x0  [NB*64*HW];
__device__ __align__(16) float g_tmp [NB*64*HW];
__device__ __align__(16) float g_x1  [NB*64*HW];
__device__ __align__(16) float g_xlt [NB*HW*64];   // xl in NHWC for gathers
__device__ __align__(16) float g_xrt [NB*HW*64];   // xr in NHWC
__device__ __align__(16) float g_dlT [576*64];     // deform weights [k*64+c][o]
__device__ __align__(16) float g_drT [576*64];
// conv weights transposed to [(ic4*9 + j)*OCP + oc] float4(4 ic)
__device__ __align__(16) float g_cw  [1474560];

// offsets (in floats) into g_cw
#define CW_OFFL  0
#define CW_OFFR  221184
#define CW_CV    442368
#define CW_RB11  884736
#define CW_RB12  1032192
#define CW_RB21  1179648
#define CW_RB22  1327104

// ---------------- NCHW -> NHWC transpose (per n: 64 x 16384 -> 16384 x 64) --
__global__ void k_transpose(const float* __restrict__ in, float* __restrict__ out)
{
    __shared__ float tile[32][33];
    int n  = blockIdx.z;
    int c0 = blockIdx.y * 32;
    int p0 = blockIdx.x * 32;
    int tx = threadIdx.x, ty = threadIdx.y;
    const float* src = in  + n*64*HW;
    float*       dst = out + n*HW*64;
    #pragma unroll
    for (int i = 0; i < 32; i += 8)
        tile[ty+i][tx] = src[(c0+ty+i)*HW + p0 + tx];
    __syncthreads();
    #pragma unroll
    for (int i = 0; i < 32; i += 8)
        dst[(p0+ty+i)*64 + c0 + tx] = tile[tx][ty+i];
}

// ---------------- deform weight transpose: w[o][c][k] -> wT[(k*64+c)*64+o] --
__global__ void k_prep_wT(const float* __restrict__ w, float* __restrict__ wT)
{
    int i = blockIdx.x*256 + threadIdx.x;
    if (i < 576*64){
        int o  = i & 63;
        int kc = i >> 6;
        int c  = kc & 63;
        int k  = kc >> 6;
        wT[i] = w[(o*64 + c)*9 + k];
    }
}

// ---------------- conv weight transpose to ic4-vectorized layout ------------
// wT float index: ((ic4*9 + j)*OCP + oc)*4 + l  <-  w[(oc*Cin + ic4*4+l)*9 + j]
__global__ void k_prep_cw(const float* __restrict__ w, float* __restrict__ wT,
                          int Cin, int Cout, int OCP, int total)
{
    int i = blockIdx.x*256 + threadIdx.x;
    if (i >= total) return;
    int l  = i & 3;
    int q  = i >> 2;
    int oc = q % OCP;
    int r2 = q / OCP;
    int j  = r2 % 9;
    int ic4 = r2 / 9;
    wT[i] = (oc < Cout) ? w[(oc*Cin + ic4*4 + l)*9 + j] : 0.f;
}

// ---------------- upsample(2x nearest) + 2x2 conv + pad(bottom/right) ------
__global__ void k_upconv(const float* __restrict__ xd, const float* __restrict__ w,
                         const float* __restrict__ bias, float* __restrict__ out)
{
    __shared__ float4 s_w4[2048];        // 16 oc x 128 ic x 4 taps
    __shared__ float  s_in[9*18];
    int n      = blockIdx.z;
    int ocBase = blockIdx.y * 16;
    int tx0 = (blockIdx.x & 3) * 32;
    int ty0 = (blockIdx.x >> 2) * 16;
    int t  = threadIdx.x;
    int lx = t & 31, ly = t >> 5;

    float* s_w = (float*)s_w4;
    for (int i = t; i < 8192; i += 256) s_w[i] = w[ocBase*512 + i];
    __syncthreads();

    const float* src = xd + n*128*4096;
    float accA[16], accB[16];
    #pragma unroll
    for (int oc = 0; oc < 16; oc++){ accA[oc] = 0.f; accB[oc] = 0.f; }

    int X  = tx0 + lx;
    int YA = ty0 + ly, YB = ty0 + ly + 8;
    bool doA = (YA < 127) && (X < 127);
    bool doB = (YB < 127) && (X < 127);
    int x0r = lx >> 1,      x1r = (lx+1) >> 1;
    int yA0 = ly >> 1,      yA1 = (ly+1) >> 1;
    int yB0 = (ly+8) >> 1,  yB1 = (ly+9) >> 1;

    for (int ic = 0; ic < 128; ic++){
        const float* p = src + ic*4096;
        if (t < 162){
            int r = t/18, c = t - r*18;
            int gy = (ty0>>1) + r, gx = (tx0>>1) + c;
            s_in[t] = (gy < 64 && gx < 64) ? p[gy*64 + gx] : 0.f;
        }
        __syncthreads();
        if (doA){
            float v00 = s_in[yA0*18+x0r], v01 = s_in[yA0*18+x1r];
            float v10 = s_in[yA1*18+x0r], v11 = s_in[yA1*18+x1r];
            #pragma unroll
            for (int oc = 0; oc < 16; oc++){
                float4 wv = s_w4[oc*128 + ic];
                accA[oc] += wv.x*v00 + wv.y*v01 + wv.z*v10 + wv.w*v11;
            }
        }
        if (doB){
            float v00 = s_in[yB0*18+x0r], v01 = s_in[yB0*18+x1r];
            float v10 = s_in[yB1*18+x0r], v11 = s_in[yB1*18+x1r];
            #pragma unroll
            for (int oc = 0; oc < 16; oc++){
                float4 wv = s_w4[oc*128 + ic];
                accB[oc] += wv.x*v00 + wv.y*v01 + wv.z*v10 + wv.w*v11;
            }
        }
        __syncthreads();
    }
    #pragma unroll
    for (int oc = 0; oc < 16; oc++){
        int o = ocBase + oc;
        float bv = bias[o];
        out[(n*64+o)*HW + YA*128 + X] = doA ? (accA[oc] + bv) : 0.f;
        out[(n*64+o)*HW + YB*128 + X] = doB ? (accB[oc] + bv) : 0.f;
    }
}

// ---------------- 3x3 conv, pad 1, ic-vectorized (float4 over 4 ic) ---------
// Tile 32 wide x (8*PX) tall, 16 oc per block, 256 threads.
// Each thread: PX pixels (rows ly, ly+8, ...) x 16 oc accumulators.
// Weights pre-transposed: wT[(ic4*9 + j)*OCP + oc] is float4 of 4 ic.
template<int PX>
__global__ void __launch_bounds__(256)
k_conv3x3v(const float* __restrict__ in0, const float* __restrict__ in1,
           const float* __restrict__ in2, int nin,
           const float4* __restrict__ wT, int OCP,
           const float* __restrict__ bias,
           float* __restrict__ out, int Cout,
           const float* __restrict__ res, int relu)
{
    const int TH = PX*8;
    const int INROWS = TH + 2;
    const int INELEMS = INROWS * 34;
    __shared__ float4 s_in[INELEMS];
    __shared__ float4 s_w[144];

    int n      = blockIdx.z;
    int ocBase = blockIdx.y * 16;
    int tx0 = (blockIdx.x & 3) * 32;
    int ty0 = (blockIdx.x >> 2) * TH;
    int t  = threadIdx.x;
    int lx = t & 31, ly = t >> 5;
    int Cin = nin * 64;

    float acc[PX][16];
    #pragma unroll
    for (int k = 0; k < PX; k++)
        #pragma unroll
        for (int oc = 0; oc < 16; oc++) acc[k][oc] = 0.f;

    for (int ic4 = 0; ic4 < (Cin >> 2); ic4++){
        int ic = ic4 << 2;
        const float* src = (ic < 64) ? in0 : ((ic < 128) ? in1 : in2);
        src += (n*64 + (ic & 63)) * HW;
        for (int i = t; i < INELEMS; i += 256){
            int r = i / 34, c = i - r*34;
            int gy = ty0 + r - 1, gx = tx0 + c - 1;
            float4 v = make_float4(0.f, 0.f, 0.f, 0.f);
            if ((unsigned)gy < 128u && (unsigned)gx < 128u){
                int o = gy*128 + gx;
                v.x = src[o];
                v.y = src[o + HW];
                v.z = src[o + 2*HW];
                v.w = src[o + 3*HW];
            }
            s_in[i] = v;
        }
        if (t < 144)
            s_w[t] = wT[(ic4*9 + (t >> 4)) * OCP + ocBase + (t & 15)];
        __syncthreads();

        #pragma unroll
        for (int j = 0; j < 9; j++){
            int rr = j/3, cc = j - rr*3;
            float4 iv[PX];
            #pragma unroll
            for (int k = 0; k < PX; k++)
                iv[k] = s_in[(ly + k*8 + rr)*34 + lx + cc];
            #pragma unroll
            for (int oc = 0; oc < 16; oc++){
                float4 wv = s_w[j*16 + oc];
                #pragma unroll
                for (int k = 0; k < PX; k++){
                    acc[k][oc] = fmaf(wv.x, iv[k].x, acc[k][oc]);
                    acc[k][oc] = fmaf(wv.y, iv[k].y, acc[k][oc]);
                    acc[k][oc] = fmaf(wv.z, iv[k].z, acc[k][oc]);
                    acc[k][oc] = fmaf(wv.w, iv[k].w, acc[k][oc]);
                }
            }
        }
        __syncthreads();
    }

    int X = tx0 + lx;
    #pragma unroll
    for (int oc = 0; oc < 16; oc++){
        int o = ocBase + oc;
        if (o < Cout){
            float bv = bias[o];
            #pragma unroll
            for (int k = 0; k < PX; k++){
                int y = ty0 + ly + k*8;
                int idx = (n*Cout + o)*HW + y*128 + X;
                float v = acc[k][oc] + bv;
                if (res)  v += res[idx];
                if (relu) v = fmaxf(v, 0.f);
                out[idx] = v;
            }
        }
    }
}

// ---------------- modulated deformable 3x3 conv ------------------------------
__global__ void k_deform(const float* __restrict__ xt, const float* __restrict__ off,
                         const float* __restrict__ wT, const float* __restrict__ bias,
                         float* __restrict__ out)
{
    extern __shared__ float smem[];
    float* s_samp = smem;                 // 16*576 = 9216 floats
    float* s_w    = smem + 9216;          // 144*64 = 9216 floats (kc chunk)
    float* s_wy   = smem + 18432;
    float* s_wx   = s_wy + 144;
    float* s_m    = s_wx + 144;
    int*   s_iy   = (int*)(s_m + 144);
    int*   s_ix   = s_iy + 144;

    int n  = blockIdx.z;
    int y0 = blockIdx.y * 2;
    int x0 = blockIdx.x * 8;
    int t  = threadIdx.x;

    if (t < 144){
        int p = t / 9, k = t - p*9;
        int yy = y0 + (p >> 3), xx = x0 + (p & 7);
        const float* ob = off + n*27*HW + yy*128 + xx;
        float dyv = ob[(2*k)*HW];
        float dxv = ob[(2*k+1)*HW];
        float mv  = 1.f / (1.f + __expf(-ob[(18+k)*HW]));
        float py = dyv + (float)(k/3) - 1.f + (float)yy;
        float px = dxv + (float)(k%3) - 1.f + (float)xx;
        float fy = floorf(py), fx = floorf(px);
        s_iy[t] = (int)fy;  s_ix[t] = (int)fx;
        s_wy[t] = py - fy;  s_wx[t] = px - fx;
        s_m[t]  = mv;
    }
    __syncthreads();

    int lane = t & 31, wrp = t >> 5;
    const float2* xb = (const float2*)(xt + n*HW*64);
    float2* s_samp2 = (float2*)s_samp;
    for (int pp = wrp; pp < 16; pp += 8){
        #pragma unroll
        for (int k = 0; k < 9; k++){
            int pk = pp*9 + k;
            int iy0 = s_iy[pk], ix0 = s_ix[pk];
            float wy = s_wy[pk], wx = s_wx[pk], m = s_m[pk];
            float w00 = (1.f-wy)*(1.f-wx);
            float w01 = (1.f-wy)*wx;
            float w10 = wy*(1.f-wx);
            float w11 = wy*wx;
            float ax = 0.f, ay = 0.f;
            int iy1 = iy0 + 1, ix1 = ix0 + 1;
            bool y0v = (unsigned)iy0 < 128u, y1v = (unsigned)iy1 < 128u;
            bool x0v = (unsigned)ix0 < 128u, x1v = (unsigned)ix1 < 128u;
            if (y0v && x0v){ float2 v = xb[(iy0*128+ix0)*32 + lane]; ax += w00*v.x; ay += w00*v.y; }
            if (y0v && x1v){ float2 v = xb[(iy0*128+ix1)*32 + lane]; ax += w01*v.x; ay += w01*v.y; }
            if (y1v && x0v){ float2 v = xb[(iy1*128+ix0)*32 + lane]; ax += w10*v.x; ay += w10*v.y; }
            if (y1v && x1v){ float2 v = xb[(iy1*128+ix1)*32 + lane]; ax += w11*v.x; ay += w11*v.y; }
            s_samp2[pp*288 + k*32 + lane] = make_float2(m*ax, m*ay);
        }
    }
    __syncthreads();

    float2 a0 = make_float2(0.f, 0.f), a1 = make_float2(0.f, 0.f);
    int pA = wrp, pB = wrp + 8;
    for (int ch = 0; ch < 4; ch++){
        const float4* wsrc = (const float4*)(wT + ch*144*64);
        float4* wdst = (float4*)s_w;
        for (int i = t; i < 2304; i += 256) wdst[i] = wsrc[i];
        __syncthreads();
        const float2* w2 = (const float2*)s_w;
        const float* sA = s_samp + pA*576 + ch*144;
        const float* sB = s_samp + pB*576 + ch*144;
        #pragma unroll 8
        for (int kc = 0; kc < 144; kc++){
            float v0 = sA[kc];
            float v1 = sB[kc];
            float2 wv = w2[kc*32 + lane];
            a0.x = fmaf(wv.x, v0, a0.x);
            a0.y = fmaf(wv.y, v0, a0.y);
            a1.x = fmaf(wv.x, v1, a1.x);
            a1.y = fmaf(wv.y, v1, a1.y);
        }
        __syncthreads();
    }
    int o0 = 2*lane;
    float b0 = bias[o0], b1 = bias[o0+1];
    {
        int yy = y0 + (pA >> 3), xx = x0 + (pA & 7);
        int base = n*64*HW + yy*128 + xx;
        out[base + o0*HW]     = a0.x + b0;
        out[base + (o0+1)*HW] = a0.y + b1;
    }
    {
        int yy = y0 + (pB >> 3), xx = x0 + (pB & 7);
        int base = n*64*HW + yy*128 + xx;
        out[base + o0*HW]     = a1.x + b0;
        out[base + (o0+1)*HW] = a1.y + b1;
    }
}

// ---------------------------------------------------------------------------
extern "C" void kernel_launch(void* const* d_in, const int* in_sizes, int n_in,
                              void* d_out, int out_size)
{
    const float* xd     = (const float*)d_in[0];
    const float* xl     = (const float*)d_in[1];
    const float* xr     = (const float*)d_in[2];
    const float* up_w   = (const float*)d_in[3];
    const float* up_b   = (const float*)d_in[4];
    const float* offl_w = (const float*)d_in[5];
    const float* offl_b = (const float*)d_in[6];
    const float* dl_w   = (const float*)d_in[7];
    const float* dl_b   = (const float*)d_in[8];
    const float* offr_w = (const float*)d_in[9];
    const float* offr_b = (const float*)d_in[10];
    const float* dr_w   = (const float*)d_in[11];
    const float* dr_b   = (const float*)d_in[12];
    const float* cv_w   = (const float*)d_in[13];
    const float* cv_b   = (const float*)d_in[14];

    // Residual-block params: setup_inputs() order is weights first
    // (rb1_w1, rb1_w2, rb2_w1, rb2_w2) then biases. Detect via sizes.
    const float *rb1_w1, *rb1_b1, *rb1_w2, *rb1_b2;
    const float *rb2_w1, *rb2_b1, *rb2_w2, *rb2_b2;
    if (in_sizes[16] == 64){
        rb1_w1 = (const float*)d_in[15]; rb1_b1 = (const float*)d_in[16];
        rb1_w2 = (const float*)d_in[17]; rb1_b2 = (const float*)d_in[18];
        rb2_w1 = (const float*)d_in[19]; rb2_b1 = (const float*)d_in[20];
        rb2_w2 = (const float*)d_in[21]; rb2_b2 = (const float*)d_in[22];
    } else {
        rb1_w1 = (const float*)d_in[15]; rb1_w2 = (const float*)d_in[16];
        rb2_w1 = (const float*)d_in[17]; rb2_w2 = (const float*)d_in[18];
        rb1_b1 = (const float*)d_in[19]; rb1_b2 = (const float*)d_in[20];
        rb2_b1 = (const float*)d_in[21]; rb2_b2 = (const float*)d_in[22];
    }

    float *p_xd, *p_off, *p_xl2, *p_xr2, *p_x0, *p_tmp, *p_x1, *p_xlt, *p_xrt, *p_dlT, *p_drT, *p_cw;
    cudaGetSymbolAddress((void**)&p_xd,  g_xd);
    cudaGetSymbolAddress((void**)&p_off, g_off);
    cudaGetSymbolAddress((void**)&p_xl2, g_xl2);
    cudaGetSymbolAddress((void**)&p_xr2, g_xr2);
    cudaGetSymbolAddress((void**)&p_x0,  g_x0);
    cudaGetSymbolAddress((void**)&p_tmp, g_tmp);
    cudaGetSymbolAddress((void**)&p_x1,  g_x1);
    cudaGetSymbolAddress((void**)&p_xlt, g_xlt);
    cudaGetSymbolAddress((void**)&p_xrt, g_xrt);
    cudaGetSymbolAddress((void**)&p_dlT, g_dlT);
    cudaGetSymbolAddress((void**)&p_drT, g_drT);
    cudaGetSymbolAddress((void**)&p_cw,  g_cw);

    cudaFuncSetAttribute(k_deform, cudaFuncAttributeMaxDynamicSharedMemorySize, 76608);

    dim3 tb(32, 8);
    // Prep: NHWC transposes, deform weight transposes, conv-weight transposes
    k_transpose<<<dim3(512, 2, 2), tb>>>(xl, p_xlt);
    k_transpose<<<dim3(512, 2, 2), tb>>>(xr, p_xrt);
    k_prep_wT<<<144, 256>>>(dl_w, p_dlT);
    k_prep_wT<<<144, 256>>>(dr_w, p_drT);

    // conv weight re-layouts: total = Cin*9*OCP floats
    k_prep_cw<<<(221184+255)/256, 256>>>(offl_w, p_cw + CW_OFFL, 192, 27, 32, 221184);
    k_prep_cw<<<(221184+255)/256, 256>>>(offr_w, p_cw + CW_OFFR, 192, 27, 32, 221184);
    k_prep_cw<<<(442368+255)/256, 256>>>(cv_w,   p_cw + CW_CV,   192, 64, 64, 442368);
    k_prep_cw<<<(147456+255)/256, 256>>>(rb1_w1, p_cw + CW_RB11,  64, 64, 64, 147456);
    k_prep_cw<<<(147456+255)/256, 256>>>(rb1_w2, p_cw + CW_RB12,  64, 64, 64, 147456);
    k_prep_cw<<<(147456+255)/256, 256>>>(rb2_w1, p_cw + CW_RB21,  64, 64, 64, 147456);
    k_prep_cw<<<(147456+255)/256, 256>>>(rb2_w2, p_cw + CW_RB22,  64, 64, 64, 147456);

    k_upconv<<<dim3(32, 4, 2), 256>>>(xd, up_w, up_b, p_xd);

    // Left branch: offset conv (192->27, PX=2) then deformable conv
    k_conv3x3v<2><<<dim3(32, 2, 2), 256>>>(xl, xr, p_xd, 3,
        (const float4*)(p_cw + CW_OFFL), 32, offl_b, p_off, 27, nullptr, 0);
    k_deform<<<dim3(16, 64, 2), 256, 76608>>>(p_xlt, p_off, p_dlT, dl_b, p_xl2);

    // Right branch
    k_conv3x3v<2><<<dim3(32, 2, 2), 256>>>(p_xl2, xr, p_xd, 3,
        (const float4*)(p_cw + CW_OFFR), 32, offr_b, p_off, 27, nullptr, 0);
    k_deform<<<dim3(16, 64, 2), 256, 76608>>>(p_xrt, p_off, p_drT, dr_b, p_xr2);

    // Fuse conv (192->64) + ReLU
    k_conv3x3v<4><<<dim3(16, 4, 2), 256>>>(p_xl2, p_xr2, p_xd, 3,
        (const float4*)(p_cw + CW_CV), 64, cv_b, p_x0, 64, nullptr, 1);

    // Residual block 1
    k_conv3x3v<4><<<dim3(16, 4, 2), 256>>>(p_x0,  nullptr, nullptr, 1,
        (const float4*)(p_cw + CW_RB11), 64, rb1_b1, p_tmp, 64, nullptr, 1);
    k_conv3x3v<4><<<dim3(16, 4, 2), 256>>>(p_tmp, nullptr, nullptr, 1,
        (const float4*)(p_cw + CW_RB12), 64, rb1_b2, p_x1, 64, p_x0, 0);

    // Residual block 2 (final conv writes straight to d_out)
    k_conv3x3v<4><<<dim3(16, 4, 2), 256>>>(p_x1,  nullptr, nullptr, 1,
        (const float4*)(p_cw + CW_RB21), 64, rb2_b1, p_tmp, 64, nullptr, 1);
    k_conv3x3v<4><<<dim3(16, 4, 2), 256>>>(p_tmp, nullptr, nullptr, 1,
        (const float4*)(p_cw + CW_RB22), 64, rb2_b2, (float*)d_out, 64, p_x1, 0);
}

// round 6
// speedup vs baseline: 1.8282x; 1.2770x over previous
#include <cuda_runtime.h>
#include <cstdint>

#define HW 16384
#define NB 2
#define CSTR 320

// ---------------- scratch (device globals; no allocations allowed) ----------
// NHWC concat buffer, per pixel 320 ch: [xl(0) | xr(64) | xd(128) | xl2(192) | xr2(256)]
__device__ __align__(16) float g_nhwc[NB*HW*CSTR];
__device__ __align__(16) float g_offb[NB*HW*32];   // offset conv out, NHWC32
__device__ __align__(16) float g_x0  [NB*HW*64];   // NHWC64
__device__ __align__(16) float g_tmp [NB*HW*64];
__device__ __align__(16) float g_x1  [NB*HW*64];
__device__ __align__(16) float g_dlT [576*64];     // deform weights [k*64+c][o]
__device__ __align__(16) float g_drT [576*64];
__device__ __align__(16) float g_wp  [737280];     // mma-frag-order conv weights (hi+lo)

// float offsets into g_wp
#define WP_OFFL 0
#define WP_OFFR 110592
#define WP_CV   221184
#define WP_RB11 442368
#define WP_RB12 516096
#define WP_RB21 589824
#define WP_RB22 663552

// ---------------- helpers ----------------------------------------------------
__device__ __forceinline__ float tf32r(float x){
    uint32_t u; asm("cvt.rna.tf32.f32 %0, %1;" : "=r"(u) : "f"(x));
    return __uint_as_float(u);
}
__device__ __forceinline__ void mma1688(float* d, const float* a, const float2 b){
    asm volatile(
      "mma.sync.aligned.m16n8k8.row.col.f32.tf32.tf32.f32 "
      "{%0,%1,%2,%3}, {%4,%5,%6,%7}, {%8,%9}, {%0,%1,%2,%3};"
      : "+f"(d[0]), "+f"(d[1]), "+f"(d[2]), "+f"(d[3])
      : "r"(__float_as_uint(a[0])), "r"(__float_as_uint(a[1])),
        "r"(__float_as_uint(a[2])), "r"(__float_as_uint(a[3])),
        "r"(__float_as_uint(b.x)),  "r"(__float_as_uint(b.y)));
}

// ---------------- NCHW 64ch -> NHWC concat cols -----------------------------
__global__ void k_transpose(const float* __restrict__ in, float* __restrict__ out, int coloff)
{
    __shared__ float tile[32][33];
    int n  = blockIdx.z;
    int c0 = blockIdx.y * 32;
    int p0 = blockIdx.x * 32;
    int tx = threadIdx.x, ty = threadIdx.y;
    const float* src = in  + (size_t)n*64*HW;
    float*       dst = out + (size_t)n*HW*CSTR;
    #pragma unroll
    for (int i = 0; i < 32; i += 8)
        tile[ty+i][tx] = src[(c0+ty+i)*HW + p0 + tx];
    __syncthreads();
    #pragma unroll
    for (int i = 0; i < 32; i += 8)
        dst[(size_t)(p0+ty+i)*CSTR + coloff + c0 + tx] = tile[tx][ty+i];
}

// ---------------- deform weight transpose: w[o][c][k] -> wT[(k*64+c)*64+o] --
__global__ void k_prep_wT(const float* __restrict__ w, float* __restrict__ wT)
{
    int i = blockIdx.x*256 + threadIdx.x;
    if (i < 576*64){
        int o  = i & 63;
        int kc = i >> 6;
        int c  = kc & 63;
        int k  = kc >> 6;
        wT[i] = w[(o*64 + c)*9 + k];
    }
}

// ---------------- conv weights -> mma fragment order (hi+lo) ----------------
// chunk q = j*nic + ib (j = tap, ib = 64-ch input block).
// Within chunk: hi half then lo half, each per = NP*64 floats.
// Fragment order: float2 (b0,b1) at index ((ks*(NP/8) + ntg)*32 + lane):
//   b0 = w[oc = ntg*8 + lane>>2][ch = ks*8 + (lane&3)],  b1 = same ch+4.
__global__ void k_prep_wtc(const float* __restrict__ w, float* __restrict__ wp,
                           int Cin, int Cout, int NP, int total)
{
    int i = blockIdx.x*256 + threadIdx.x;
    if (i >= total) return;
    int per = NP*64;
    int q  = i / per;
    int r  = i - q*per;
    int b   = r & 1;
    int tq  = r >> 1;
    int lane = tq & 31;
    int u    = tq >> 5;
    int ntg  = u % (NP >> 3);
    int ks   = u / (NP >> 3);
    int oc = ntg*8 + (lane >> 2);
    int ch = ks*8 + (lane & 3) + b*4;
    int nic = Cin >> 6;
    int j  = q / nic;
    int ib = q - j*nic;
    float v = (oc < Cout) ? w[((size_t)oc*Cin + ib*64 + ch)*9 + j] : 0.f;
    float hi = tf32r(v);
    float lo = tf32r(v - hi);
    size_t base = (size_t)q * 2 * per;
    wp[base + r]       = hi;
    wp[base + per + r] = lo;
}

// ---------------- upsample(2x nearest) + 2x2 conv + pad -> NHWC cols 128-191
__global__ void k_upconv(const float* __restrict__ xd, const float* __restrict__ w,
                         const float* __restrict__ bias, float* __restrict__ out)
{
    __shared__ float4 s_w4[2048];        // 16 oc x 128 ic x 4 taps
    __shared__ float  s_in[9*18];
    int n      = blockIdx.z;
    int ocBase = blockIdx.y * 16;
    int tx0 = (blockIdx.x & 3) * 32;
    int ty0 = (blockIdx.x >> 2) * 16;
    int t  = threadIdx.x;
    int lx = t & 31, ly = t >> 5;

    float* s_w = (float*)s_w4;
    for (int i = t; i < 8192; i += 256) s_w[i] = w[ocBase*512 + i];
    __syncthreads();

    const float* src = xd + (size_t)n*128*4096;
    float accA[16], accB[16];
    #pragma unroll
    for (int oc = 0; oc < 16; oc++){ accA[oc] = 0.f; accB[oc] = 0.f; }

    int X  = tx0 + lx;
    int YA = ty0 + ly, YB = ty0 + ly + 8;
    bool doA = (YA < 127) && (X < 127);
    bool doB = (YB < 127) && (X < 127);
    int x0r = lx >> 1,      x1r = (lx+1) >> 1;
    int yA0 = ly >> 1,      yA1 = (ly+1) >> 1;
    int yB0 = (ly+8) >> 1,  yB1 = (ly+9) >> 1;

    for (int ic = 0; ic < 128; ic++){
        const float* p = src + ic*4096;
        if (t < 162){
            int r = t/18, c = t - r*18;
            int gy = (ty0>>1) + r, gx = (tx0>>1) + c;
            s_in[t] = (gy < 64 && gx < 64) ? p[gy*64 + gx] : 0.f;
        }
        __syncthreads();
        if (doA){
            float v00 = s_in[yA0*18+x0r], v01 = s_in[yA0*18+x1r];
            float v10 = s_in[yA1*18+x0r], v11 = s_in[yA1*18+x1r];
            #pragma unroll
            for (int oc = 0; oc < 16; oc++){
                float4 wv = s_w4[oc*128 + ic];
                accA[oc] += wv.x*v00 + wv.y*v01 + wv.z*v10 + wv.w*v11;
            }
        }
        if (doB){
            float v00 = s_in[yB0*18+x0r], v01 = s_in[yB0*18+x1r];
            float v10 = s_in[yB1*18+x0r], v11 = s_in[yB1*18+x1r];
            #pragma unroll
            for (int oc = 0; oc < 16; oc++){
                float4 wv = s_w4[oc*128 + ic];
                accB[oc] += wv.x*v00 + wv.y*v01 + wv.z*v10 + wv.w*v11;
            }
        }
        __syncthreads();
    }
    float* ob = out + (size_t)n*HW*CSTR;
    #pragma unroll
    for (int oc = 0; oc < 16; oc++){
        int o = ocBase + oc;
        float bv = bias[o];
        ob[(size_t)(YA*128+X)*CSTR + 128 + o] = doA ? (accA[oc] + bv) : 0.f;
        ob[(size_t)(YB*128+X)*CSTR + 128 + o] = doB ? (accB[oc] + bv) : 0.f;
    }
}

// ---------------- mma.sync TF32 implicit-GEMM 3x3 conv ----------------------
// Block: one image row y. M=128 px, N=NP oc. 8 warps = 4 M-splits x 2 N-splits.
// Warp computes 32 px x NP/2 oc via m16n8k8 tiles; 3xTF32 split for accuracy.
// A staged fp32 in smem as [4ch-region][130 px] (halo x), restaged per (ib,dy).
// B staged per (ib,tap): flat copy of pre-packed fragment-order hi/lo chunk.
template<int NP>
__global__ void __launch_bounds__(256)
k_convMMA(const float* __restrict__ in, int inStride,
          int co0, int co1, int co2, int nicblk,
          const float* __restrict__ wp,
          const float* __restrict__ bias,
          float* __restrict__ out, int outStride, int outCol, int outNCHW, int Cout,
          const float* __restrict__ res, int relu)
{
    constexpr int NT  = NP/16;       // n tiles per warp
    constexpr int per = NP*64;       // floats per B half-chunk
    constexpr int A_BYTES = 16*130*16;   // 16 regions x 130 px x 16B = 33280
    extern __shared__ char smem[];
    char*  sA = smem;
    float* sB = (float*)(smem + A_BYTES);

    int t = threadIdx.x, lane = t & 31, wrp = t >> 5;
    int mw = wrp & 3, nw = wrp >> 2;
    int g = lane >> 2, tig = lane & 3;
    int y = blockIdx.x, n = blockIdx.z;
    const float* inN = in + (size_t)n*HW*inStride;
    int cos[3] = {co0, co1, co2};

    float d[2][NT][4];
    #pragma unroll
    for (int mt = 0; mt < 2; mt++)
        #pragma unroll
        for (int nt = 0; nt < NT; nt++)
            #pragma unroll
            for (int k = 0; k < 4; k++) d[mt][nt][k] = 0.f;

    for (int ib = 0; ib < nicblk; ib++){
        int co = cos[ib];
        for (int dy = 0; dy < 3; dy++){
            int ys = y + dy - 1;
            bool yv = (unsigned)ys < 128u;
            __syncthreads();                    // prior readers of sA done
            for (int i = t; i < 2080; i += 256){
                int c4 = i / 130, s = i - c4*130;
                int x = s - 1;
                float4 v = make_float4(0.f, 0.f, 0.f, 0.f);
                if (yv && (unsigned)x < 128u)
                    v = *(const float4*)(inN + (size_t)(ys*128 + x)*inStride + co + c4*4);
                *(float4*)(sA + c4*2080 + s*16) = v;
            }
            for (int dx = 0; dx < 3; dx++){
                int q = (dy*3 + dx)*nicblk + ib;
                __syncthreads();                // sA staged; prior sB readers done
                {
                    const float4* ws = (const float4*)(wp + (size_t)q*2*per);
                    for (int i = t; i < NP*32; i += 256) ((float4*)sB)[i] = ws[i];
                }
                __syncthreads();
                int s0 = mw*32 + g + dx;
                #pragma unroll
                for (int ks = 0; ks < 8; ks++){
                    float ah[2][4], al[2][4];
                    #pragma unroll
                    for (int mt = 0; mt < 2; mt++){
                        const char* base = sA + (2*ks)*2080 + (s0 + mt*16)*16 + tig*4;
                        float a0 = *(const float*)(base);
                        float a1 = *(const float*)(base + 128);
                        float a2 = *(const float*)(base + 2080);
                        float a3 = *(const float*)(base + 2208);
                        ah[mt][0] = tf32r(a0); al[mt][0] = tf32r(a0 - ah[mt][0]);
                        ah[mt][1] = tf32r(a1); al[mt][1] = tf32r(a1 - ah[mt][1]);
                        ah[mt][2] = tf32r(a2); al[mt][2] = tf32r(a2 - ah[mt][2]);
                        ah[mt][3] = tf32r(a3); al[mt][3] = tf32r(a3 - ah[mt][3]);
                    }
                    float2 bh[NT], bl[NT];
                    #pragma unroll
                    for (int nt = 0; nt < NT; nt++){
                        int idx = (ks*(NP>>3) + nw*NT + nt)*32 + lane;
                        bh[nt] = ((const float2*)sB)[idx];
                        bl[nt] = ((const float2*)sB)[idx + per/2];
                    }
                    #pragma unroll
                    for (int mt = 0; mt < 2; mt++)
                        #pragma unroll
                        for (int nt = 0; nt < NT; nt++){
                            mma1688(d[mt][nt], ah[mt], bh[nt]);
                            mma1688(d[mt][nt], ah[mt], bl[nt]);
                            mma1688(d[mt][nt], al[mt], bh[nt]);
                        }
                }
            }
        }
    }

    // ---- epilogue ----
    #pragma unroll
    for (int mt = 0; mt < 2; mt++){
        int p0 = y*128 + mw*32 + mt*16 + g;
        int p1 = p0 + 8;
        #pragma unroll
        for (int nt = 0; nt < NT; nt++){
            int oc0 = nw*(NP/2) + nt*8 + 2*tig;
            float v00 = d[mt][nt][0], v01 = d[mt][nt][1];
            float v10 = d[mt][nt][2], v11 = d[mt][nt][3];
            float b0v = (oc0   < Cout) ? bias[oc0]   : 0.f;
            float b1v = (oc0+1 < Cout) ? bias[oc0+1] : 0.f;
            v00 += b0v; v01 += b1v; v10 += b0v; v11 += b1v;
            if (res){
                v00 += res[((size_t)n*HW + p0)*64 + oc0];
                v01 += res[((size_t)n*HW + p0)*64 + oc0 + 1];
                v10 += res[((size_t)n*HW + p1)*64 + oc0];
                v11 += res[((size_t)n*HW + p1)*64 + oc0 + 1];
            }
            if (relu){
                v00 = fmaxf(v00, 0.f); v01 = fmaxf(v01, 0.f);
                v10 = fmaxf(v10, 0.f); v11 = fmaxf(v11, 0.f);
            }
            if (outNCHW){
                if (oc0 < Cout){
                    out[((size_t)n*Cout + oc0)*HW + p0] = v00;
                    out[((size_t)n*Cout + oc0)*HW + p1] = v10;
                }
                if (oc0 + 1 < Cout){
                    out[((size_t)n*Cout + oc0+1)*HW + p0] = v01;
                    out[((size_t)n*Cout + oc0+1)*HW + p1] = v11;
                }
            } else {
                float* o0 = out + ((size_t)n*HW + p0)*outStride + outCol;
                float* o1 = out + ((size_t)n*HW + p1)*outStride + outCol;
                if (oc0 + 1 < Cout){
                    *(float2*)(o0 + oc0) = make_float2(v00, v01);
                    *(float2*)(o1 + oc0) = make_float2(v10, v11);
                } else if (oc0 < Cout){
                    o0[oc0] = v00; o1[oc0] = v10;
                }
            }
        }
    }
}

// ---------------- modulated deformable 3x3 conv ------------------------------
__global__ void k_deform(const float* __restrict__ nhwc, int xco,
                         const float* __restrict__ off,
                         const float* __restrict__ wT, const float* __restrict__ bias,
                         float* __restrict__ out, int oco)
{
    extern __shared__ char smem[];
    float* smf = (float*)smem;
    float* s_samp = smf;                  // 16*576 = 9216 floats
    float* s_w    = smf + 9216;           // 144*64 = 9216 floats (kc chunk)
    float* s_wy   = smf + 18432;
    float* s_wx   = s_wy + 144;
    float* s_m    = s_wx + 144;
    int*   s_iy   = (int*)(s_m + 144);
    int*   s_ix   = s_iy + 144;

    int n  = blockIdx.z;
    int y0 = blockIdx.y * 2;
    int x0 = blockIdx.x * 8;
    int t  = threadIdx.x;

    if (t < 144){
        int p = t / 9, k = t - p*9;
        int yy = y0 + (p >> 3), xx = x0 + (p & 7);
        const float* ob = off + ((size_t)n*HW + yy*128 + xx)*32;
        float dyv = ob[2*k];
        float dxv = ob[2*k+1];
        float mv  = 1.f / (1.f + __expf(-ob[18+k]));
        float py = dyv + (float)(k/3) - 1.f + (float)yy;
        float px = dxv + (float)(k%3) - 1.f + (float)xx;
        float fy = floorf(py), fx = floorf(px);
        s_iy[t] = (int)fy;  s_ix[t] = (int)fx;
        s_wy[t] = py - fy;  s_wx[t] = px - fx;
        s_m[t]  = mv;
    }
    __syncthreads();

    int lane = t & 31, wrp = t >> 5;
    const float2* xb = (const float2*)(nhwc + (size_t)n*HW*CSTR + xco);  // idx: pix*160 + lane
    float2* s_samp2 = (float2*)s_samp;
    for (int pp = wrp; pp < 16; pp += 8){
        #pragma unroll
        for (int k = 0; k < 9; k++){
            int pk = pp*9 + k;
            int iy0 = s_iy[pk], ix0 = s_ix[pk];
            float wy = s_wy[pk], wx = s_wx[pk], m = s_m[pk];
            float w00 = (1.f-wy)*(1.f-wx);
            float w01 = (1.f-wy)*wx;
            float w10 = wy*(1.f-wx);
            float w11 = wy*wx;
            float ax = 0.f, ay = 0.f;
            int iy1 = iy0 + 1, ix1 = ix0 + 1;
            bool y0v = (unsigned)iy0 < 128u, y1v = (unsigned)iy1 < 128u;
            bool x0v = (unsigned)ix0 < 128u, x1v = (unsigned)ix1 < 128u;
            if (y0v && x0v){ float2 v = xb[(size_t)(iy0*128+ix0)*160 + lane]; ax += w00*v.x; ay += w00*v.y; }
            if (y0v && x1v){ float2 v = xb[(size_t)(iy0*128+ix1)*160 + lane]; ax += w01*v.x; ay += w01*v.y; }
            if (y1v && x0v){ float2 v = xb[(size_t)(iy1*128+ix0)*160 + lane]; ax += w10*v.x; ay += w10*v.y; }
            if (y1v && x1v){ float2 v = xb[(size_t)(iy1*128+ix1)*160 + lane]; ax += w11*v.x; ay += w11*v.y; }
            s_samp2[pp*288 + k*32 + lane] = make_float2(m*ax, m*ay);
        }
    }
    __syncthreads();

    float2 a0 = make_float2(0.f, 0.f), a1 = make_float2(0.f, 0.f);
    int pA = wrp, pB = wrp + 8;
    for (int ch = 0; ch < 4; ch++){
        const float4* wsrc = (const float4*)(wT + ch*144*64);
        float4* wdst = (float4*)s_w;
        for (int i = t; i < 2304; i += 256) wdst[i] = wsrc[i];
        __syncthreads();
        const float2* w2 = (const float2*)s_w;
        const float* sA = s_samp + pA*576 + ch*144;
        const float* sB = s_samp + pB*576 + ch*144;
        #pragma unroll 8
        for (int kc = 0; kc < 144; kc++){
            float v0 = sA[kc];
            float v1 = sB[kc];
            float2 wv = w2[kc*32 + lane];
            a0.x = fmaf(wv.x, v0, a0.x);
            a0.y = fmaf(wv.y, v0, a0.y);
            a1.x = fmaf(wv.x, v1, a1.x);
            a1.y = fmaf(wv.y, v1, a1.y);
        }
        __syncthreads();
    }
    int o0 = 2*lane;
    float b0 = bias[o0], b1 = bias[o0+1];
    {
        int yy = y0 + (pA >> 3), xx = x0 + (pA & 7);
        float* op = out + ((size_t)n*HW + yy*128 + xx)*CSTR + oco + o0;
        *(float2*)op = make_float2(a0.x + b0, a0.y + b1);
    }
    {
        int yy = y0 + (pB >> 3), xx = x0 + (pB & 7);
        float* op = out + ((size_t)n*HW + yy*128 + xx)*CSTR + oco + o0;
        *(float2*)op = make_float2(a1.x + b0, a1.y + b1);
    }
}

// ---------------------------------------------------------------------------
extern "C" void kernel_launch(void* const* d_in, const int* in_sizes, int n_in,
                              void* d_out, int out_size)
{
    const float* xd     = (const float*)d_in[0];
    const float* xl     = (const float*)d_in[1];
    const float* xr     = (const float*)d_in[2];
    const float* up_w   = (const float*)d_in[3];
    const float* up_b   = (const float*)d_in[4];
    const float* offl_w = (const float*)d_in[5];
    const float* offl_b = (const float*)d_in[6];
    const float* dl_w   = (const float*)d_in[7];
    const float* dl_b   = (const float*)d_in[8];
    const float* offr_w = (const float*)d_in[9];
    const float* offr_b = (const float*)d_in[10];
    const float* dr_w   = (const float*)d_in[11];
    const float* dr_b   = (const float*)d_in[12];
    const float* cv_w   = (const float*)d_in[13];
    const float* cv_b   = (const float*)d_in[14];

    const float *rb1_w1, *rb1_b1, *rb1_w2, *rb1_b2;
    const float *rb2_w1, *rb2_b1, *rb2_w2, *rb2_b2;
    if (in_sizes[16] == 64){
        rb1_w1 = (const float*)d_in[15]; rb1_b1 = (const float*)d_in[16];
        rb1_w2 = (const float*)d_in[17]; rb1_b2 = (const float*)d_in[18];
        rb2_w1 = (const float*)d_in[19]; rb2_b1 = (const float*)d_in[20];
        rb2_w2 = (const float*)d_in[21]; rb2_b2 = (const float*)d_in[22];
    } else {
        rb1_w1 = (const float*)d_in[15]; rb1_w2 = (const float*)d_in[16];
        rb2_w1 = (const float*)d_in[17]; rb2_w2 = (const float*)d_in[18];
        rb1_b1 = (const float*)d_in[19]; rb1_b2 = (const float*)d_in[20];
        rb2_b1 = (const float*)d_in[21]; rb2_b2 = (const float*)d_in[22];
    }

    float *p_nhwc, *p_off, *p_x0, *p_tmp, *p_x1, *p_dlT, *p_drT, *p_wp;
    cudaGetSymbolAddress((void**)&p_nhwc, g_nhwc);
    cudaGetSymbolAddress((void**)&p_off,  g_offb);
    cudaGetSymbolAddress((void**)&p_x0,   g_x0);
    cudaGetSymbolAddress((void**)&p_tmp,  g_tmp);
    cudaGetSymbolAddress((void**)&p_x1,   g_x1);
    cudaGetSymbolAddress((void**)&p_dlT,  g_dlT);
    cudaGetSymbolAddress((void**)&p_drT,  g_drT);
    cudaGetSymbolAddress((void**)&p_wp,   g_wp);

    cudaFuncSetAttribute(k_deform, cudaFuncAttributeMaxDynamicSharedMemorySize, 76608);
    cudaFuncSetAttribute(k_convMMA<64>, cudaFuncAttributeMaxDynamicSharedMemorySize, 66304);
    cudaFuncSetAttribute(k_convMMA<32>, cudaFuncAttributeMaxDynamicSharedMemorySize, 49920);

    dim3 tb(32, 8);
    // NHWC staging of xl, xr
    k_transpose<<<dim3(512, 2, 2), tb>>>(xl, p_nhwc, 0);
    k_transpose<<<dim3(512, 2, 2), tb>>>(xr, p_nhwc, 64);
    // deform weights
    k_prep_wT<<<144, 256>>>(dl_w, p_dlT);
    k_prep_wT<<<144, 256>>>(dr_w, p_drT);
    // mma conv weight chunks (fragment order, hi+lo)
    k_prep_wtc<<<216, 256>>>(offl_w, p_wp + WP_OFFL, 192, 27, 32,  55296);
    k_prep_wtc<<<216, 256>>>(offr_w, p_wp + WP_OFFR, 192, 27, 32,  55296);
    k_prep_wtc<<<432, 256>>>(cv_w,   p_wp + WP_CV,   192, 64, 64, 110592);
    k_prep_wtc<<<144, 256>>>(rb1_w1, p_wp + WP_RB11,  64, 64, 64,  36864);
    k_prep_wtc<<<144, 256>>>(rb1_w2, p_wp + WP_RB12,  64, 64, 64,  36864);
    k_prep_wtc<<<144, 256>>>(rb2_w1, p_wp + WP_RB21,  64, 64, 64,  36864);
    k_prep_wtc<<<144, 256>>>(rb2_w2, p_wp + WP_RB22,  64, 64, 64,  36864);
    // upsample-conv -> NHWC cols 128-191
    k_upconv<<<dim3(32, 4, 2), 256>>>(xd, up_w, up_b, p_nhwc);

    dim3 cg(128, 1, 2);
    // Left: offset conv (192->27) on [xl|xr|xd], then deform xl -> cols 192
    k_convMMA<32><<<cg, 256, 49920>>>(p_nhwc, CSTR, 0, 64, 128, 3, p_wp + WP_OFFL,
                                      offl_b, p_off, 32, 0, 0, 27, nullptr, 0);
    k_deform<<<dim3(16, 64, 2), 256, 76608>>>(p_nhwc, 0,   p_off, p_dlT, dl_b, p_nhwc, 192);
    // Right: offset conv on [xl2|xr|xd], then deform xr -> cols 256
    k_convMMA<32><<<cg, 256, 49920>>>(p_nhwc, CSTR, 192, 64, 128, 3, p_wp + WP_OFFR,
                                      offr_b, p_off, 32, 0, 0, 27, nullptr, 0);
    k_deform<<<dim3(16, 64, 2), 256, 76608>>>(p_nhwc, 64,  p_off, p_drT, dr_b, p_nhwc, 256);
    // Fuse conv (192->64) + ReLU on [xl2|xr2|xd] -> x0 (NHWC64)
    k_convMMA<64><<<cg, 256, 66304>>>(p_nhwc, CSTR, 192, 256, 128, 3, p_wp + WP_CV,
                                      cv_b, p_x0, 64, 0, 0, 64, nullptr, 1);
    // Residual block 1
    k_convMMA<64><<<cg, 256, 66304>>>(p_x0,  64, 0, 0, 0, 1, p_wp + WP_RB11,
                                      rb1_b1, p_tmp, 64, 0, 0, 64, nullptr, 1);
    k_convMMA<64><<<cg, 256, 66304>>>(p_tmp, 64, 0, 0, 0, 1, p_wp + WP_RB12,
                                      rb1_b2, p_x1, 64, 0, 0, 64, p_x0, 0);
    // Residual block 2 (final conv writes NCHW straight to d_out)
    k_convMMA<64><<<cg, 256, 66304>>>(p_x1,  64, 0, 0, 0, 1, p_wp + WP_RB21,
                                      rb2_b1, p_tmp, 64, 0, 0, 64, nullptr, 1);
    k_convMMA<64><<<cg, 256, 66304>>>(p_tmp, 64, 0, 0, 0, 1, p_wp + WP_RB22,
                                      rb2_b2, (float*)d_out, 64, 0, 1, 64, p_x1, 0);
}

// round 7
// speedup vs baseline: 1.9146x; 1.0473x over previous
#include <cuda_runtime.h>
#include <cstdint>

#define HW 16384
#define NB 2
#define CSTR 320

// ---------------- scratch (device globals; no allocations allowed) ----------
// NHWC concat buffer, per pixel 320 ch: [xl(0) | xr(64) | xd(128) | xl2(192) | xr2(256)]
__device__ __align__(16) float g_nhwc[NB*HW*CSTR];
__device__ __align__(16) float g_offb[NB*HW*32];   // offset conv out, NHWC32
__device__ __align__(16) float g_x0  [NB*HW*64];   // NHWC64
__device__ __align__(16) float g_tmp [NB*HW*64];
__device__ __align__(16) float g_x1  [NB*HW*64];
__device__ __align__(16) float g_dlT [576*64];     // deform weights [k*64+c][o]
__device__ __align__(16) float g_drT [576*64];
__device__ __align__(16) float g_wp  [737280];     // mma-frag-order conv weights (hi+lo)

// float offsets into g_wp
#define WP_OFFL 0
#define WP_OFFR 110592
#define WP_CV   221184
#define WP_RB11 442368
#define WP_RB12 516096
#define WP_RB21 589824
#define WP_RB22 663552

// ---------------- helpers ----------------------------------------------------
__device__ __forceinline__ float tf32r(float x){
    uint32_t u; asm("cvt.rna.tf32.f32 %0, %1;" : "=r"(u) : "f"(x));
    return __uint_as_float(u);
}
__device__ __forceinline__ void mma1688(float* d, const float* a, const float2 b){
    asm volatile(
      "mma.sync.aligned.m16n8k8.row.col.f32.tf32.tf32.f32 "
      "{%0,%1,%2,%3}, {%4,%5,%6,%7}, {%8,%9}, {%0,%1,%2,%3};"
      : "+f"(d[0]), "+f"(d[1]), "+f"(d[2]), "+f"(d[3])
      : "r"(__float_as_uint(a[0])), "r"(__float_as_uint(a[1])),
        "r"(__float_as_uint(a[2])), "r"(__float_as_uint(a[3])),
        "r"(__float_as_uint(b.x)),  "r"(__float_as_uint(b.y)));
}

// ---------------- device bodies for prep tasks -------------------------------
__device__ __forceinline__ void body_prep_wT(const float* __restrict__ w,
                                             float* __restrict__ wT, int i)
{
    if (i < 576*64){
        int o  = i & 63;
        int kc = i >> 6;
        int c  = kc & 63;
        int k  = kc >> 6;
        wT[i] = w[(o*64 + c)*9 + k];
    }
}

// fragment-order (hi+lo) conv weight pack; see k_convMMA for layout
__device__ __forceinline__ void body_prep_wtc(const float* __restrict__ w,
                                              float* __restrict__ wp,
                                              int Cin, int Cout, int NP, int i)
{
    int per = NP*64;
    int q  = i / per;
    int r  = i - q*per;
    int b   = r & 1;
    int tq  = r >> 1;
    int lane = tq & 31;
    int u    = tq >> 5;
    int ntg  = u % (NP >> 3);
    int ks   = u / (NP >> 3);
    int oc = ntg*8 + (lane >> 2);
    int ch = ks*8 + (lane & 3) + b*4;
    int nic = Cin >> 6;
    int j  = q / nic;
    int ib = q - j*nic;
    float v = (oc < Cout) ? w[((size_t)oc*Cin + ib*64 + ch)*9 + j] : 0.f;
    float hi = tf32r(v);
    float lo = tf32r(v - hi);
    size_t base = (size_t)q * 2 * per;
    wp[base + r]       = hi;
    wp[base + per + r] = lo;
}

// ---------------- one merged prep kernel (all independent re-layouts) --------
// blocks: [0,2048) transpose xl | [2048,4096) transpose xr |
// [4096,4240) wT dl | [4240,4384) wT dr |
// [4384,4600) wtc offl | [4600,4816) wtc offr | [4816,5248) wtc cv |
// [5248,5392) rb11 | [5392,5536) rb12 | [5536,5680) rb21 | [5680,5824) rb22
__global__ void __launch_bounds__(256)
k_prep_all(const float* __restrict__ xl, const float* __restrict__ xr,
           float* __restrict__ nhwc,
           const float* __restrict__ dl_w, const float* __restrict__ dr_w,
           float* __restrict__ dlT, float* __restrict__ drT,
           const float* __restrict__ offl_w, const float* __restrict__ offr_w,
           const float* __restrict__ cv_w,
           const float* __restrict__ r11, const float* __restrict__ r12,
           const float* __restrict__ r21, const float* __restrict__ r22,
           float* __restrict__ wp)
{
    __shared__ float tile[32][33];
    int b = blockIdx.x, t = threadIdx.x;
    if (b < 4096){
        const float* in = (b < 2048) ? xl : xr;
        int coloff = (b < 2048) ? 0 : 64;
        int bb = b & 2047;
        int n  = bb >> 10;
        int c0 = ((bb >> 9) & 1) * 32;
        int p0 = (bb & 511) * 32;
        int tx = t & 31, ty = t >> 5;
        const float* src = in + (size_t)n*64*HW;
        float* dst = nhwc + (size_t)n*HW*CSTR;
        #pragma unroll
        for (int i = 0; i < 32; i += 8)
            tile[ty+i][tx] = src[(c0+ty+i)*HW + p0 + tx];
        __syncthreads();
        #pragma unroll
        for (int i = 0; i < 32; i += 8)
            dst[(size_t)(p0+ty+i)*CSTR + coloff + c0 + tx] = tile[tx][ty+i];
    } else if (b < 4240){
        body_prep_wT(dl_w, dlT, (b-4096)*256 + t);
    } else if (b < 4384){
        body_prep_wT(dr_w, drT, (b-4240)*256 + t);
    } else if (b < 4600){
        body_prep_wtc(offl_w, wp + WP_OFFL, 192, 27, 32, (b-4384)*256 + t);
    } else if (b < 4816){
        body_prep_wtc(offr_w, wp + WP_OFFR, 192, 27, 32, (b-4600)*256 + t);
    } else if (b < 5248){
        body_prep_wtc(cv_w,   wp + WP_CV,   192, 64, 64, (b-4816)*256 + t);
    } else if (b < 5392){
        body_prep_wtc(r11,    wp + WP_RB11,  64, 64, 64, (b-5248)*256 + t);
    } else if (b < 5536){
        body_prep_wtc(r12,    wp + WP_RB12,  64, 64, 64, (b-5392)*256 + t);
    } else if (b < 5680){
        body_prep_wtc(r21,    wp + WP_RB21,  64, 64, 64, (b-5536)*256 + t);
    } else {
        body_prep_wtc(r22,    wp + WP_RB22,  64, 64, 64, (b-5680)*256 + t);
    }
}

// ---------------- upsample(2x nearest) + 2x2 conv + pad -> NHWC cols 128-191
__global__ void k_upconv(const float* __restrict__ xd, const float* __restrict__ w,
                         const float* __restrict__ bias, float* __restrict__ out)
{
    __shared__ float4 s_w4[2048];        // 16 oc x 128 ic x 4 taps
    __shared__ float  s_in[9*18];
    int n      = blockIdx.z;
    int ocBase = blockIdx.y * 16;
    int tx0 = (blockIdx.x & 3) * 32;
    int ty0 = (blockIdx.x >> 2) * 16;
    int t  = threadIdx.x;
    int lx = t & 31, ly = t >> 5;

    float* s_w = (float*)s_w4;
    for (int i = t; i < 8192; i += 256) s_w[i] = w[ocBase*512 + i];
    __syncthreads();

    const float* src = xd + (size_t)n*128*4096;
    float accA[16], accB[16];
    #pragma unroll
    for (int oc = 0; oc < 16; oc++){ accA[oc] = 0.f; accB[oc] = 0.f; }

    int X  = tx0 + lx;
    int YA = ty0 + ly, YB = ty0 + ly + 8;
    bool doA = (YA < 127) && (X < 127);
    bool doB = (YB < 127) && (X < 127);
    int x0r = lx >> 1,      x1r = (lx+1) >> 1;
    int yA0 = ly >> 1,      yA1 = (ly+1) >> 1;
    int yB0 = (ly+8) >> 1,  yB1 = (ly+9) >> 1;

    for (int ic = 0; ic < 128; ic++){
        const float* p = src + ic*4096;
        if (t < 162){
            int r = t/18, c = t - r*18;
            int gy = (ty0>>1) + r, gx = (tx0>>1) + c;
            s_in[t] = (gy < 64 && gx < 64) ? p[gy*64 + gx] : 0.f;
        }
        __syncthreads();
        if (doA){
            float v00 = s_in[yA0*18+x0r], v01 = s_in[yA0*18+x1r];
            float v10 = s_in[yA1*18+x0r], v11 = s_in[yA1*18+x1r];
            #pragma unroll
            for (int oc = 0; oc < 16; oc++){
                float4 wv = s_w4[oc*128 + ic];
                accA[oc] += wv.x*v00 + wv.y*v01 + wv.z*v10 + wv.w*v11;
            }
        }
        if (doB){
            float v00 = s_in[yB0*18+x0r], v01 = s_in[yB0*18+x1r];
            float v10 = s_in[yB1*18+x0r], v11 = s_in[yB1*18+x1r];
            #pragma unroll
            for (int oc = 0; oc < 16; oc++){
                float4 wv = s_w4[oc*128 + ic];
                accB[oc] += wv.x*v00 + wv.y*v01 + wv.z*v10 + wv.w*v11;
            }
        }
        __syncthreads();
    }
    float* ob = out + (size_t)n*HW*CSTR;
    #pragma unroll
    for (int oc = 0; oc < 16; oc++){
        int o = ocBase + oc;
        float bv = bias[o];
        ob[(size_t)(YA*128+X)*CSTR + 128 + o] = doA ? (accA[oc] + bv) : 0.f;
        ob[(size_t)(YB*128+X)*CSTR + 128 + o] = doB ? (accB[oc] + bv) : 0.f;
    }
}

// ---------------- mma.sync TF32 implicit-GEMM 3x3 conv ----------------------
// Block: one image row y. M=128 px, N=NP oc. 8 warps = 4 M-splits x 2 N-splits.
// A pre-split hi/lo at staging, pair-packed: float2 (ch tig, ch tig+4) per px.
//   sAh/sAl layout: [ks(8)][px_mem(130)][tig(4)] float2.
// B staged per (ib,tap): flat copy of pre-packed fragment-order hi/lo chunk.
template<int NP>
__global__ void __launch_bounds__(256)
k_convMMA(const float* __restrict__ in, int inStride,
          int co0, int co1, int co2, int nicblk,
          const float* __restrict__ wp,
          const float* __restrict__ bias,
          float* __restrict__ out, int outStride, int outCol, int outNCHW, int Cout,
          const float* __restrict__ res, int relu)
{
    constexpr int NT  = NP/16;       // n tiles per warp
    constexpr int per = NP*64;       // floats per B half-chunk
    constexpr int A_FLOAT2 = 8*130*4;        // 4160 float2 per buffer
    extern __shared__ char smem[];
    float2* sAh = (float2*)smem;
    float2* sAl = sAh + A_FLOAT2;
    float*  sB  = (float*)(sAl + A_FLOAT2);

    int t = threadIdx.x, lane = t & 31, wrp = t >> 5;
    int mw = wrp & 3, nw = wrp >> 2;
    int g = lane >> 2, tig = lane & 3;
    int y = blockIdx.x, n = blockIdx.z;
    const float* inN = in + (size_t)n*HW*inStride;
    int cos[3] = {co0, co1, co2};

    float d[2][NT][4];
    #pragma unroll
    for (int mt = 0; mt < 2; mt++)
        #pragma unroll
        for (int nt = 0; nt < NT; nt++)
            #pragma unroll
            for (int k = 0; k < 4; k++) d[mt][nt][k] = 0.f;

    for (int ib = 0; ib < nicblk; ib++){
        int co = cos[ib];
        for (int dy = 0; dy < 3; dy++){
            int ys = y + dy - 1;
            bool yv = (unsigned)ys < 128u;
            __syncthreads();                    // prior readers of sA done
            // stage A: 130 px x 8 ks-groups, hi/lo split + pair packing
            for (int i = t; i < 1040; i += 256){
                int ks = i / 130, s = i - ks*130;
                int x = s - 1;
                float4 v0 = make_float4(0.f,0.f,0.f,0.f);
                float4 v1 = make_float4(0.f,0.f,0.f,0.f);
                if (yv && (unsigned)x < 128u){
                    const float* p = inN + (size_t)(ys*128 + x)*inStride + co + ks*8;
                    v0 = *(const float4*)p;
                    v1 = *(const float4*)(p + 4);
                }
                int base = (ks*130 + s)*4;
                float2 h, l;
                h.x = tf32r(v0.x); l.x = tf32r(v0.x - h.x);
                h.y = tf32r(v1.x); l.y = tf32r(v1.x - h.y);
                sAh[base+0] = h; sAl[base+0] = l;
                h.x = tf32r(v0.y); l.x = tf32r(v0.y - h.x);
                h.y = tf32r(v1.y); l.y = tf32r(v1.y - h.y);
                sAh[base+1] = h; sAl[base+1] = l;
                h.x = tf32r(v0.z); l.x = tf32r(v0.z - h.x);
                h.y = tf32r(v1.z); l.y = tf32r(v1.z - h.y);
                sAh[base+2] = h; sAl[base+2] = l;
                h.x = tf32r(v0.w); l.x = tf32r(v0.w - h.x);
                h.y = tf32r(v1.w); l.y = tf32r(v1.w - h.y);
                sAh[base+3] = h; sAl[base+3] = l;
            }
            for (int dx = 0; dx < 3; dx++){
                int q = (dy*3 + dx)*nicblk + ib;
                __syncthreads();                // sA staged; prior sB readers done
                {
                    const float4* ws = (const float4*)(wp + (size_t)q*2*per);
                    for (int i = t; i < NP*32; i += 256) ((float4*)sB)[i] = ws[i];
                }
                __syncthreads();
                int s0 = mw*32 + g + dx;
                #pragma unroll
                for (int ks = 0; ks < 8; ks++){
                    float ah[2][4], al[2][4];
                    #pragma unroll
                    for (int mt = 0; mt < 2; mt++){
                        int bi = (ks*130 + s0 + mt*16)*4 + tig;
                        float2 hg  = sAh[bi];
                        float2 hg8 = sAh[bi + 32];
                        float2 lg  = sAl[bi];
                        float2 lg8 = sAl[bi + 32];
                        ah[mt][0] = hg.x;  ah[mt][1] = hg8.x;
                        ah[mt][2] = hg.y;  ah[mt][3] = hg8.y;
                        al[mt][0] = lg.x;  al[mt][1] = lg8.x;
                        al[mt][2] = lg.y;  al[mt][3] = lg8.y;
                    }
                    float2 bh[NT], bl[NT];
                    #pragma unroll
                    for (int nt = 0; nt < NT; nt++){
                        int idx = (ks*(NP>>3) + nw*NT + nt)*32 + lane;
                        bh[nt] = ((const float2*)sB)[idx];
                        bl[nt] = ((const float2*)sB)[idx + per/2];
                    }
                    #pragma unroll
                    for (int mt = 0; mt < 2; mt++)
                        #pragma unroll
                        for (int nt = 0; nt < NT; nt++){
                            mma1688(d[mt][nt], ah[mt], bh[nt]);
                            mma1688(d[mt][nt], ah[mt], bl[nt]);
                            mma1688(d[mt][nt], al[mt], bh[nt]);
                        }
                }
            }
        }
    }

    // ---- epilogue ----
    #pragma unroll
    for (int mt = 0; mt < 2; mt++){
        int p0 = y*128 + mw*32 + mt*16 + g;
        int p1 = p0 + 8;
        #pragma unroll
        for (int nt = 0; nt < NT; nt++){
            int oc0 = nw*(NP/2) + nt*8 + 2*tig;
            float v00 = d[mt][nt][0], v01 = d[mt][nt][1];
            float v10 = d[mt][nt][2], v11 = d[mt][nt][3];
            float b0v = (oc0   < Cout) ? bias[oc0]   : 0.f;
            float b1v = (oc0+1 < Cout) ? bias[oc0+1] : 0.f;
            v00 += b0v; v01 += b1v; v10 += b0v; v11 += b1v;
            if (res){
                v00 += res[((size_t)n*HW + p0)*64 + oc0];
                v01 += res[((size_t)n*HW + p0)*64 + oc0 + 1];
                v10 += res[((size_t)n*HW + p1)*64 + oc0];
                v11 += res[((size_t)n*HW + p1)*64 + oc0 + 1];
            }
            if (relu){
                v00 = fmaxf(v00, 0.f); v01 = fmaxf(v01, 0.f);
                v10 = fmaxf(v10, 0.f); v11 = fmaxf(v11, 0.f);
            }
            if (outNCHW){
                if (oc0 < Cout){
                    out[((size_t)n*Cout + oc0)*HW + p0] = v00;
                    out[((size_t)n*Cout + oc0)*HW + p1] = v10;
                }
                if (oc0 + 1 < Cout){
                    out[((size_t)n*Cout + oc0+1)*HW + p0] = v01;
                    out[((size_t)n*Cout + oc0+1)*HW + p1] = v11;
                }
            } else {
                float* o0 = out + ((size_t)n*HW + p0)*outStride + outCol;
                float* o1 = out + ((size_t)n*HW + p1)*outStride + outCol;
                if (oc0 + 1 < Cout){
                    *(float2*)(o0 + oc0) = make_float2(v00, v01);
                    *(float2*)(o1 + oc0) = make_float2(v10, v11);
                } else if (oc0 < Cout){
                    o0[oc0] = v00; o1[oc0] = v10;
                }
            }
        }
    }
}

// ---------------- modulated deformable 3x3 conv ------------------------------
// Weights read straight from L1/L2 (coalesced, shared across blocks) -> small
// smem (39KB) -> 4-5 blocks/SM to hide the scattered bilinear gathers.
__global__ void k_deform(const float* __restrict__ nhwc, int xco,
                         const float* __restrict__ off,
                         const float* __restrict__ wT, const float* __restrict__ bias,
                         float* __restrict__ out, int oco)
{
    extern __shared__ char smem[];
    float* smf = (float*)smem;
    float* s_samp = smf;                  // 16*576 = 9216 floats
    float* s_wy   = smf + 9216;
    float* s_wx   = s_wy + 144;
    float* s_m    = s_wx + 144;
    int*   s_iy   = (int*)(s_m + 144);
    int*   s_ix   = s_iy + 144;

    int n  = blockIdx.z;
    int y0 = blockIdx.y * 2;
    int x0 = blockIdx.x * 8;
    int t  = threadIdx.x;

    if (t < 144){
        int p = t / 9, k = t - p*9;
        int yy = y0 + (p >> 3), xx = x0 + (p & 7);
        const float* ob = off + ((size_t)n*HW + yy*128 + xx)*32;
        float dyv = ob[2*k];
        float dxv = ob[2*k+1];
        float mv  = 1.f / (1.f + __expf(-ob[18+k]));
        float py = dyv + (float)(k/3) - 1.f + (float)yy;
        float px = dxv + (float)(k%3) - 1.f + (float)xx;
        float fy = floorf(py), fx = floorf(px);
        s_iy[t] = (int)fy;  s_ix[t] = (int)fx;
        s_wy[t] = py - fy;  s_wx[t] = px - fx;
        s_m[t]  = mv;
    }
    __syncthreads();

    int lane = t & 31, wrp = t >> 5;
    const float2* xb = (const float2*)(nhwc + (size_t)n*HW*CSTR + xco);  // idx: pix*160 + lane
    float2* s_samp2 = (float2*)s_samp;
    for (int pp = wrp; pp < 16; pp += 8){
        #pragma unroll
        for (int k = 0; k < 9; k++){
            int pk = pp*9 + k;
            int iy0 = s_iy[pk], ix0 = s_ix[pk];
            float wy = s_wy[pk], wx = s_wx[pk], m = s_m[pk];
            float w00 = (1.f-wy)*(1.f-wx);
            float w01 = (1.f-wy)*wx;
            float w10 = wy*(1.f-wx);
            float w11 = wy*wx;
            float ax = 0.f, ay = 0.f;
            int iy1 = iy0 + 1, ix1 = ix0 + 1;
            bool y0v = (unsigned)iy0 < 128u, y1v = (unsigned)iy1 < 128u;
            bool x0v = (unsigned)ix0 < 128u, x1v = (unsigned)ix1 < 128u;
            if (y0v && x0v){ float2 v = xb[(size_t)(iy0*128+ix0)*160 + lane]; ax += w00*v.x; ay += w00*v.y; }
            if (y0v && x1v){ float2 v = xb[(size_t)(iy0*128+ix1)*160 + lane]; ax += w01*v.x; ay += w01*v.y; }
            if (y1v && x0v){ float2 v = xb[(size_t)(iy1*128+ix0)*160 + lane]; ax += w10*v.x; ay += w10*v.y; }
            if (y1v && x1v){ float2 v = xb[(size_t)(iy1*128+ix1)*160 + lane]; ax += w11*v.x; ay += w11*v.y; }
            s_samp2[pp*288 + k*32 + lane] = make_float2(m*ax, m*ay);
        }
    }
    __syncthreads();

    float2 a0 = make_float2(0.f, 0.f), a1 = make_float2(0.f, 0.f);
    int pA = wrp, pB = wrp + 8;
    const float2* w2 = (const float2*)wT;     // [(ch*144+kc)*32 + lane]
    for (int ch = 0; ch < 4; ch++){
        const float* sA = s_samp + pA*576 + ch*144;
        const float* sB = s_samp + pB*576 + ch*144;
        #pragma unroll 4
        for (int kc = 0; kc < 144; kc++){
            float v0 = sA[kc];
            float v1 = sB[kc];
            float2 wv = __ldg(&w2[(ch*144 + kc)*32 + lane]);
            a0.x = fmaf(wv.x, v0, a0.x);
            a0.y = fmaf(wv.y, v0, a0.y);
            a1.x = fmaf(wv.x, v1, a1.x);
            a1.y = fmaf(wv.y, v1, a1.y);
        }
    }
    int o0 = 2*lane;
    float b0 = bias[o0], b1 = bias[o0+1];
    {
        int yy = y0 + (pA >> 3), xx = x0 + (pA & 7);
        float* op = out + ((size_t)n*HW + yy*128 + xx)*CSTR + oco + o0;
        *(float2*)op = make_float2(a0.x + b0, a0.y + b1);
    }
    {
        int yy = y0 + (pB >> 3), xx = x0 + (pB & 7);
        float* op = out + ((size_t)n*HW + yy*128 + xx)*CSTR + oco + o0;
        *(float2*)op = make_float2(a1.x + b0, a1.y + b1);
    }
}

// ---------------------------------------------------------------------------
extern "C" void kernel_launch(void* const* d_in, const int* in_sizes, int n_in,
                              void* d_out, int out_size)
{
    const float* xd     = (const float*)d_in[0];
    const float* xl     = (const float*)d_in[1];
    const float* xr     = (const float*)d_in[2];
    const float* up_w   = (const float*)d_in[3];
    const float* up_b   = (const float*)d_in[4];
    const float* offl_w = (const float*)d_in[5];
    const float* offl_b = (const float*)d_in[6];
    const float* dl_w   = (const float*)d_in[7];
    const float* dl_b   = (const float*)d_in[8];
    const float* offr_w = (const float*)d_in[9];
    const float* offr_b = (const float*)d_in[10];
    const float* dr_w   = (const float*)d_in[11];
    const float* dr_b   = (const float*)d_in[12];
    const float* cv_w   = (const float*)d_in[13];
    const float* cv_b   = (const float*)d_in[14];

    const float *rb1_w1, *rb1_b1, *rb1_w2, *rb1_b2;
    const float *rb2_w1, *rb2_b1, *rb2_w2, *rb2_b2;
    if (in_sizes[16] == 64){
        rb1_w1 = (const float*)d_in[15]; rb1_b1 = (const float*)d_in[16];
        rb1_w2 = (const float*)d_in[17]; rb1_b2 = (const float*)d_in[18];
        rb2_w1 = (const float*)d_in[19]; rb2_b1 = (const float*)d_in[20];
        rb2_w2 = (const float*)d_in[21]; rb2_b2 = (const float*)d_in[22];
    } else {
        rb1_w1 = (const float*)d_in[15]; rb1_w2 = (const float*)d_in[16];
        rb2_w1 = (const float*)d_in[17]; rb2_w2 = (const float*)d_in[18];
        rb1_b1 = (const float*)d_in[19]; rb1_b2 = (const float*)d_in[20];
        rb2_b1 = (const float*)d_in[21]; rb2_b2 = (const float*)d_in[22];
    }

    float *p_nhwc, *p_off, *p_x0, *p_tmp, *p_x1, *p_dlT, *p_drT, *p_wp;
    cudaGetSymbolAddress((void**)&p_nhwc, g_nhwc);
    cudaGetSymbolAddress((void**)&p_off,  g_offb);
    cudaGetSymbolAddress((void**)&p_x0,   g_x0);
    cudaGetSymbolAddress((void**)&p_tmp,  g_tmp);
    cudaGetSymbolAddress((void**)&p_x1,   g_x1);
    cudaGetSymbolAddress((void**)&p_dlT,  g_dlT);
    cudaGetSymbolAddress((void**)&p_drT,  g_drT);
    cudaGetSymbolAddress((void**)&p_wp,   g_wp);

    // smem: A hi/lo = 2*33280 = 66560; B = NP*128*4 bytes
    const int SM64 = 66560 + 32768;   // 99328
    const int SM32 = 66560 + 16384;   // 82944
    cudaFuncSetAttribute(k_convMMA<64>, cudaFuncAttributeMaxDynamicSharedMemorySize, SM64);
    cudaFuncSetAttribute(k_convMMA<32>, cudaFuncAttributeMaxDynamicSharedMemorySize, SM32);
    const int SMD = (9216 + 5*144)*4 + 64;    // ~39.5KB

    // 1: all independent prep work in one launch
    k_prep_all<<<5824, 256>>>(xl, xr, p_nhwc, dl_w, dr_w, p_dlT, p_drT,
                              offl_w, offr_w, cv_w, rb1_w1, rb1_w2, rb2_w1, rb2_w2, p_wp);
    // 2: upsample-conv -> NHWC cols 128-191
    k_upconv<<<dim3(32, 4, 2), 256>>>(xd, up_w, up_b, p_nhwc);

    dim3 cg(128, 1, 2);
    // 3: left offset conv (192->27) on [xl|xr|xd]
    k_convMMA<32><<<cg, 256, SM32>>>(p_nhwc, CSTR, 0, 64, 128, 3, p_wp + WP_OFFL,
                                     offl_b, p_off, 32, 0, 0, 27, nullptr, 0);
    // 4: deform xl -> cols 192
    k_deform<<<dim3(16, 64, 2), 256, SMD>>>(p_nhwc, 0,   p_off, p_dlT, dl_b, p_nhwc, 192);
    // 5: right offset conv on [xl2|xr|xd]
    k_convMMA<32><<<cg, 256, SM32>>>(p_nhwc, CSTR, 192, 64, 128, 3, p_wp + WP_OFFR,
                                     offr_b, p_off, 32, 0, 0, 27, nullptr, 0);
    // 6: deform xr -> cols 256
    k_deform<<<dim3(16, 64, 2), 256, SMD>>>(p_nhwc, 64,  p_off, p_drT, dr_b, p_nhwc, 256);
    // 7: fuse conv (192->64) + ReLU on [xl2|xr2|xd] -> x0 (NHWC64)
    k_convMMA<64><<<cg, 256, SM64>>>(p_nhwc, CSTR, 192, 256, 128, 3, p_wp + WP_CV,
                                     cv_b, p_x0, 64, 0, 0, 64, nullptr, 1);
    // 8-9: residual block 1
    k_convMMA<64><<<cg, 256, SM64>>>(p_x0,  64, 0, 0, 0, 1, p_wp + WP_RB11,
                                     rb1_b1, p_tmp, 64, 0, 0, 64, nullptr, 1);
    k_convMMA<64><<<cg, 256, SM64>>>(p_tmp, 64, 0, 0, 0, 1, p_wp + WP_RB12,
                                     rb1_b2, p_x1, 64, 0, 0, 64, p_x0, 0);
    // 10-11: residual block 2 (final conv writes NCHW straight to d_out)
    k_convMMA<64><<<cg, 256, SM64>>>(p_x1,  64, 0, 0, 0, 1, p_wp + WP_RB21,
                                     rb2_b1, p_tmp, 64, 0, 0, 64, nullptr, 1);
    k_convMMA<64><<<cg, 256, SM64>>>(p_tmp, 64, 0, 0, 0, 1, p_wp + WP_RB22,
                                     rb2_b2, (float*)d_out, 64, 0, 1, 64, p_x1, 0);
}